// round 5
// baseline (speedup 1.0000x reference)
#include <cuda_runtime.h>
#include <cuda_bf16.h>

#define NB 32
#define NA 8400
#define NA4 (NA / 4)
#define NM 50
#define NC 80
#define NO 85
#define BIGC 1000000000.0f
#define BS 128
#define GX 66                  // ceil(8400/128)
#define NBLK (GX * NB)         // 2112
#define MAXENT 16384

// ---- scratch ----
__device__ float g_cost[(size_t)NB * NM * NA];
__device__ float g_iou [(size_t)NB * NM * NA];
__device__ unsigned char g_fg[NB * NA];
__device__ unsigned long long g_mask[NB * NA];
__device__ float g_pobj[NBLK];
__device__ int g_ngt[NB];
__device__ unsigned int g_ent[MAXENT];
__device__ int g_cnt;
__device__ double g_acc[4];

// -------------------------------------------------------------------------
// Per-anchor assignment; output rows staged through shared memory so all
// global loads are coalesced (row stride 340B is hostile to per-lane loads).
__global__ void __launch_bounds__(BS) kassignA(
        const float* __restrict__ outp,
        const float* __restrict__ xsh,
        const float* __restrict__ ysh,
        const float* __restrict__ est,
        const float* __restrict__ lab) {
    int b = blockIdx.y;
    __shared__ float srow[BS * NO];      // 43520 B
    __shared__ float sl[NM * 5];
    __shared__ int s_nv;

    for (int i = threadIdx.x; i < NM * 5; i += BS)
        sl[i] = lab[b * NM * 5 + i];

    int a0 = blockIdx.x * BS;
    int nrow = NA - a0; if (nrow > BS) nrow = BS;
    const float* gbase = outp + ((size_t)b * NA + a0) * NO;
    for (int i = threadIdx.x; i < nrow * NO; i += BS)
        srow[i] = gbase[i];
    __syncthreads();

    if (threadIdx.x == 0) {
        int n = 0;
        for (int m = 0; m < NM; m++) {
            float s = sl[m*5+0] + sl[m*5+1] + sl[m*5+2] + sl[m*5+3] + sl[m*5+4];
            if (s > 0.0f) n++;
        }
        s_nv = n;
        if (blockIdx.x == 0) {
            g_ngt[b] = n;
            if (b == 0) {
                g_cnt = 0;
                g_acc[0] = 0.0; g_acc[1] = 0.0; g_acc[2] = 0.0; g_acc[3] = 0.0;
            }
        }
    }
    __syncthreads();
    int nv = s_nv;   // valid gts are the prefix [0, nv)

    int tid = threadIdx.x;
    int a = a0 + tid;
    float objbase = 0.0f;

    if (tid < nrow) {
        g_mask[b * NA + a] = 0ull;
        const float* row = srow + tid * NO;
        float cx = row[0], cy = row[1], w = row[2], h = row[3], obj = row[4];
        float stride = est[a];
        float xc = (xsh[a] + 0.5f) * stride;
        float yc = (ysh[a] + 0.5f) * stride;
        float rad = 2.5f * stride;

        objbase = fmaxf(obj, 0.0f) + __logf(1.0f + __expf(-fabsf(obj)));

        unsigned long long inboth = 0ull;
        bool fg = false;
        #pragma unroll 1
        for (int m = 0; m < nv; m++) {
            float gx = sl[m*5+0], gy = sl[m*5+1], gw = sl[m*5+2], gh = sl[m*5+3];
            float hw = 0.5f * gw, hh = 0.5f * gh;
            bool ib = (xc > gx - hw) && (gx + hw > xc) && (yc > gy - hh) && (gy + hh > yc);
            bool ic = (xc > gx - rad) && (xc < gx + rad) && (yc > gy - rad) && (yc < gy + rad);
            fg = fg || ib || ic;
            if (ib && ic) inboth |= 1ull << m;
        }
        g_fg[b * NA + a] = fg ? 1 : 0;

        if (fg) {
            float eo = __expf(-obj);
            float sqrt_sigo = __frsqrt_rn(1.0f + eo);
            float lso = __logf(sqrt_sigo);

            // S = sum_c log(1-p_c), grouped products of 5
            float S = 0.0f;
            #pragma unroll 1
            for (int g = 0; g < NC; g += 5) {
                float prod = 1.0f;
                #pragma unroll
                for (int c = 0; c < 5; c++) {
                    float x = row[5 + g + c];
                    float e = __expf(-x);
                    float p = sqrt_sigo * __frsqrt_rn(1.0f + e);
                    prod *= (1.0f - p);
                }
                S += __logf(fmaxf(prod, 1e-30f));
            }

            float px1 = cx - 0.5f * w, px2 = cx + 0.5f * w;
            float py1 = cy - 0.5f * h, py2 = cy + 0.5f * h;
            float area_p = w * h;
            #pragma unroll 1
            for (int m = 0; m < nv; m++) {
                size_t off = ((size_t)b * NM + m) * NA + a;
                float gx = sl[m*5+0], gy = sl[m*5+1], gw = sl[m*5+2], gh = sl[m*5+3];
                float hw = 0.5f * gw, hh = 0.5f * gh;
                float tlx = fmaxf(gx - hw, px1), brx = fminf(gx + hw, px2);
                float tly = fmaxf(gy - hh, py1), bry = fminf(gy + hh, py2);
                float ai = ((tlx < brx) && (tly < bry)) ? (brx - tlx) * (bry - tly) : 0.0f;
                float iouv = ai / (gw * gh + area_p - ai + 1e-16f);
                int c = (int)sl[m*5+4];
                float x = row[5 + c];
                float e = __expf(-x);
                float t = 1.0f + e;
                float lg = __logf(t);
                float p = sqrt_sigo * __frsqrt_rn(t);
                float lp  = fmaxf(lso - 0.5f * lg, -100.0f);
                float l1p = fmaxf(__logf(1.0f - p), -100.0f);
                float cls_cost = -(lp + S - l1p);
                float extra = ((inboth >> m) & 1ull) ? 0.0f : 100000.0f;
                float cost = cls_cost - 3.0f * __logf(iouv + 1e-8f) + extra;
                g_iou[off] = iouv;
                g_cost[off] = cost;
            }
        }
    }

    int lane = threadIdx.x & 31, wid = threadIdx.x >> 5;
    #pragma unroll
    for (int o = 16; o > 0; o >>= 1)
        objbase += __shfl_down_sync(0xffffffffu, objbase, o);
    __shared__ float sred[4];
    if (lane == 0) sred[wid] = objbase;
    __syncthreads();
    if (threadIdx.x == 0) {
        g_pobj[blockIdx.y * GX + blockIdx.x] = sred[0] + sred[1] + sred[2] + sred[3];
    }
}

// -------------------------------------------------------------------------
// Per (gt,batch): one scan -> per-thread sorted 10-lists -> merge tree.
__global__ void kselect(const float* __restrict__ lab) {
    int m = blockIdx.x, b = blockIdx.y;
    const float* lr = lab + (b * NM + m) * 5;
    if (lr[0] + lr[1] + lr[2] + lr[3] + lr[4] <= 0.0f) return;

    size_t rowoff = ((size_t)b * NM + m) * NA;
    const float4* iou4  = (const float4*)(g_iou  + rowoff);
    const float4* cost4 = (const float4*)(g_cost + rowoff);
    const uchar4* fg4   = (const uchar4*)(g_fg + b * NA);
    int t = threadIdx.x;

    float ti[10], tc[10];
    int   tx[10];
    #pragma unroll
    for (int k = 0; k < 10; k++) { ti[k] = 0.0f; tc[k] = 3.0e38f; tx[k] = 0x7fffffff; }

    for (int i4 = t; i4 < NA4; i4 += 256) {
        uchar4 f = fg4[i4];
        if ((f.x | f.y | f.z | f.w) == 0) continue;
        float4 v4 = iou4[i4];
        float4 c4 = cost4[i4];
        float vv[4] = { f.x ? v4.x : 0.0f, f.y ? v4.y : 0.0f,
                        f.z ? v4.z : 0.0f, f.w ? v4.w : 0.0f };
        float cc[4] = { f.x ? c4.x : BIGC, f.y ? c4.y : BIGC,
                        f.z ? c4.z : BIGC, f.w ? c4.w : BIGC };
        #pragma unroll
        for (int j = 0; j < 4; j++) {
            float v = vv[j], c = cc[j];
            int   i = i4 * 4 + j;
            if (v > ti[9]) {
                float cur = v;
                #pragma unroll
                for (int k = 0; k < 10; k++)
                    if (cur > ti[k]) { float tmp = ti[k]; ti[k] = cur; cur = tmp; }
            }
            if (c < tc[9]) {
                float cv = c; int ci = i;
                #pragma unroll
                for (int k = 0; k < 10; k++) {
                    bool sw = (cv < tc[k]) || (cv == tc[k] && ci < tx[k]);
                    if (sw) {
                        float tf = tc[k]; tc[k] = cv; cv = tf;
                        int   tn = tx[k]; tx[k] = ci; ci = tn;
                    }
                }
            }
        }
    }

    __shared__ float s_v[2560];
    __shared__ float s_c[2560];
    __shared__ int   s_x[2560];
    #pragma unroll
    for (int k = 0; k < 10; k++) {
        s_v[t * 10 + k] = ti[k];
        s_c[t * 10 + k] = tc[k];
        s_x[t * 10 + k] = tx[k];
    }
    __syncthreads();

    for (int stride = 1; stride < 256; stride <<= 1) {
        if ((t & (2 * stride - 1)) == 0) {
            int A = t * 10, B = (t + stride) * 10;
            {
                float M[10]; int i = 0, j = 0;
                #pragma unroll
                for (int k = 0; k < 10; k++) {
                    float av = s_v[A + i], bv = s_v[B + j];
                    if (av >= bv) { M[k] = av; i++; } else { M[k] = bv; j++; }
                }
                #pragma unroll
                for (int k = 0; k < 10; k++) s_v[A + k] = M[k];
            }
            {
                float Mc[10]; int Mx[10]; int i = 0, j = 0;
                #pragma unroll
                for (int k = 0; k < 10; k++) {
                    float ac = s_c[A + i], bc = s_c[B + j];
                    int   ax = s_x[A + i], bx = s_x[B + j];
                    bool takeA = (ac < bc) || (ac == bc && ax < bx);
                    if (takeA) { Mc[k] = ac; Mx[k] = ax; i++; }
                    else       { Mc[k] = bc; Mx[k] = bx; j++; }
                }
                #pragma unroll
                for (int k = 0; k < 10; k++) { s_c[A + k] = Mc[k]; s_x[A + k] = Mx[k]; }
            }
        }
        __syncthreads();
    }

    if (t == 0) {
        float ksum = 0.0f;
        #pragma unroll
        for (int k = 0; k < 10; k++) ksum += s_v[k];
        int dynk = (int)ksum;
        if (dynk < 1) dynk = 1;
        if (dynk > 10) dynk = 10;

        unsigned int ents[10];
        int ns = 0;
        for (int k = 0; k < dynk; k++) {
            if (s_c[k] >= BIGC) break;
            int a = s_x[k];
            atomicOr(&g_mask[b * NA + a], 1ull << m);
            ents[ns++] = ((unsigned int)b << 20) | ((unsigned int)m << 14) | (unsigned int)a;
        }
        if (ns > 0) {
            int base = atomicAdd(&g_cnt, ns);
            for (int k = 0; k < ns; k++) g_ent[base + k] = ents[k];
        }
    }
}

// -------------------------------------------------------------------------
// Compact loss over matched entries; also folds in the g_pobj partials.
__global__ void klossC(const float* __restrict__ outp,
                       const float* __restrict__ lab) {
    int idx = blockIdx.x * blockDim.x + threadIdx.x;
    int cnt = g_cnt;
    float l_iou = 0.0f, l_obj = 0.0f, l_cls = 0.0f, nf = 0.0f;

    if (idx < NBLK) l_obj += g_pobj[idx];

    if (idx < cnt) {
        unsigned int e = g_ent[idx];
        int b = e >> 20;
        int m = (e >> 14) & 0x3f;
        int a = e & 0x3fff;
        unsigned long long mask = g_mask[b * NA + a];
        int first = __ffsll((long long)mask) - 1;
        if (m == first) {
            nf = 1.0f;
            int amg = __popcll(mask);
            const float* row = outp + ((size_t)b * NA + a) * NO;
            float obj = row[4];
            l_obj += -obj;

            int mgt;
            if (amg == 1) {
                mgt = first;
            } else {
                int ngt = g_ngt[b];
                float bv = 3.0e38f; mgt = 0;
                for (int mm = 0; mm < ngt; mm++) {
                    float c = g_cost[((size_t)b * NM + mm) * NA + a];
                    if (c < bv) { bv = c; mgt = mm; }
                }
            }
            float pious = g_iou[((size_t)b * NM + mgt) * NA + a];
            const float* lrow = lab + (b * NM + mgt) * 5;
            float gx = lrow[0], gy = lrow[1], gw = lrow[2], gh = lrow[3];
            int gc = (int)lrow[4];
            float cx = row[0], cy = row[1], w = row[2], h = row[3];
            float hw = 0.5f * gw, hh = 0.5f * gh, pw = 0.5f * w, ph = 0.5f * h;
            float tlx = fmaxf(gx - hw, cx - pw), brx = fminf(gx + hw, cx + pw);
            float tly = fmaxf(gy - hh, cy - ph), bry = fminf(gy + hh, cy + ph);
            float ai = ((tlx < brx) && (tly < bry)) ? (brx - tlx) * (bry - tly) : 0.0f;
            float iou = ai / (w * h + gw * gh - ai + 1e-16f);
            l_iou = 1.0f - iou * iou;

            float ssp = 0.0f;
            #pragma unroll 4
            for (int c = 0; c < NC; c++) {
                float x = row[5 + c];
                ssp += x + __logf(1.0f + __expf(-x));
            }
            l_cls = ssp - row[5 + gc] * pious;
        }
    }

    int lane = threadIdx.x & 31, wid = threadIdx.x >> 5;
    #pragma unroll
    for (int o = 16; o > 0; o >>= 1) {
        l_iou += __shfl_down_sync(0xffffffffu, l_iou, o);
        l_obj += __shfl_down_sync(0xffffffffu, l_obj, o);
        l_cls += __shfl_down_sync(0xffffffffu, l_cls, o);
        nf    += __shfl_down_sync(0xffffffffu, nf, o);
    }
    __shared__ float sred[8][4];
    if (lane == 0) {
        sred[wid][0] = l_iou; sred[wid][1] = l_obj;
        sred[wid][2] = l_cls; sred[wid][3] = nf;
    }
    __syncthreads();
    if (threadIdx.x == 0) {
        float p0 = 0, p1 = 0, p2 = 0, p3 = 0;
        #pragma unroll
        for (int wq = 0; wq < 8; wq++) {
            p0 += sred[wq][0]; p1 += sred[wq][1];
            p2 += sred[wq][2]; p3 += sred[wq][3];
        }
        atomicAdd(&g_acc[0], (double)p0);
        atomicAdd(&g_acc[1], (double)p1);
        atomicAdd(&g_acc[2], (double)p2);
        atomicAdd(&g_acc[3], (double)p3);
    }
}

// -------------------------------------------------------------------------
__global__ void kfin(float* out) {
    double nfg = g_acc[3];
    if (nfg < 1.0) nfg = 1.0;
    out[0] = (float)((5.0 * g_acc[0] + g_acc[1] + g_acc[2]) / nfg);
}

// -------------------------------------------------------------------------
extern "C" void kernel_launch(void* const* d_in, const int* in_sizes, int n_in,
                              void* d_out, int out_size) {
    const float* outp = (const float*)d_in[0];
    const float* xsh  = (const float*)d_in[1];
    const float* ysh  = (const float*)d_in[2];
    const float* est  = (const float*)d_in[3];
    const float* lab  = (const float*)d_in[4];
    (void)in_sizes; (void)n_in; (void)out_size;

    dim3 gA(GX, NB);
    kassignA<<<gA, BS>>>(outp, xsh, ysh, est, lab);

    dim3 gB(NM, NB);
    kselect<<<gB, 256>>>(lab);

    klossC<<<64, 256>>>(outp, lab);

    kfin<<<1, 1>>>((float*)d_out);
}